// round 14
// baseline (speedup 1.0000x reference)
#include <cuda_runtime.h>

#define BATCH 32
#define CH    512
#define HW    4096
#define BN_EPS 1e-5f

// Scratch (device global — no allocation allowed in kernel_launch)
__device__ float g_pooled[BATCH * CH];   // mean_{H,W}(x)[b,c] + m[c]

struct A7 { float a[7]; };               // 1-D bilinear-mean weights (host-computed)

// ---------------------------------------------------------------------------
// Kernel 1: per-(b,c) spatial mean of x, with the rank-1 pos-embed mean m[c]
// folded in (taps pre-scaled by HW, whole sum scaled by 1/HW at the end).
// One block per contiguous 4096-float plane; 128 threads x 8 float4 loads
// (front-batched, MLP=8, coalesced). Triggers PDL so the GEMM kernel can
// stage its weights under this kernel's tail.
// ---------------------------------------------------------------------------
__global__ void pool_kernel(const float* __restrict__ x,
                            const float* __restrict__ pos,
                            A7 aw) {
    const int idx = blockIdx.x;                      // b*CH + c
    const int c   = idx & (CH - 1);
    const float4* p = reinterpret_cast<const float4*>(x) + (size_t)idx * (HW / 4);
    const int t = threadIdx.x;

    // Issue all global loads first (front-batched).
    float4 v[8];
#pragma unroll
    for (int j = 0; j < 8; ++j)
        v[j] = p[t + 128 * j];

    // Allow the dependent GEMM kernel to begin launching/staging.
    if (t == 0) cudaTriggerProgrammaticLaunchCompletion();

    // 49-tap pos-embed contribution: thread t<49 handles tap (jy,jx).
    // Scaled by HW so it rides through the final 1/HW normalization.
    float s = 0.0f;
    if (t < 49) {
        const int jy = t / 7, jx = t - 7 * jy;
        s = aw.a[jy] * aw.a[jx] * (float)HW * __ldg(pos + c * 49 + t);
    }

#pragma unroll
    for (int j = 0; j < 8; ++j)
        s += (v[j].x + v[j].y) + (v[j].z + v[j].w);

#pragma unroll
    for (int off = 16; off; off >>= 1)
        s += __shfl_xor_sync(0xffffffffu, s, off);

    __shared__ float sh[4];
    if ((t & 31) == 0) sh[t >> 5] = s;
    __syncthreads();
    if (t == 0)
        g_pooled[idx] = ((sh[0] + sh[1]) + (sh[2] + sh[3])) * (1.0f / HW);
}

// ---------------------------------------------------------------------------
// Kernel 2 (PDL secondary): y[b,o] = dot(g_pooled[b,:], W[o,:]) + bias[o],
// then eval-mode BN + ReLU.
// Grid 64 x 256: warp w handles o = blk*8 + w for ALL 32 batches. W row lives
// in 16 registers per lane, loaded BEFORE cudaGridDependencySynchronize()
// (all 64 blocks co-resident -> full 1MB W read hides under pool via PDL).
// g_pooled traffic: 64 blocks x 64KB = 4MB L2 (was 32MB); identical lane
// addresses across warps -> L1 broadcast hits. Batch loop in groups of 4 for
// 4 concurrent shfl-reduction chains.
// ---------------------------------------------------------------------------
__global__ void gemm_bn_kernel(const float* __restrict__ w,
                               const float* __restrict__ bias,
                               const float* __restrict__ gamma,
                               const float* __restrict__ beta,
                               const float* __restrict__ mean,
                               const float* __restrict__ var,
                               float* __restrict__ out) {
    const int t = threadIdx.x;
    const int warp = t >> 5, lane = t & 31;
    const int o = blockIdx.x * 8 + warp;

    // ---- Prologue (independent of pool output): W row -> registers, BN scalars.
    const float4* wr = reinterpret_cast<const float4*>(w + o * CH);
    float4 wv[4];
#pragma unroll
    for (int j = 0; j < 4; ++j)
        wv[j] = wr[lane + 32 * j];

    const float bo  = bias[o];
    const float g   = gamma[o];
    const float bt  = beta[o];
    const float mn  = mean[o];
    const float inv = rsqrtf(var[o] + BN_EPS);

    // Wait for pool_kernel's writes to be visible (no-op without PDL).
    cudaGridDependencySynchronize();

    const float4* pooled4 = reinterpret_cast<const float4*>(g_pooled);

#pragma unroll
    for (int bb = 0; bb < BATCH; bb += 4) {
        float a0 = 0.0f, a1 = 0.0f, a2 = 0.0f, a3 = 0.0f;
#pragma unroll
        for (int j = 0; j < 4; ++j) {
            const int col = lane + 32 * j;
            float4 p0 = pooled4[(bb + 0) * (CH / 4) + col];
            float4 p1 = pooled4[(bb + 1) * (CH / 4) + col];
            float4 p2 = pooled4[(bb + 2) * (CH / 4) + col];
            float4 p3 = pooled4[(bb + 3) * (CH / 4) + col];
            a0 += p0.x * wv[j].x + p0.y * wv[j].y + p0.z * wv[j].z + p0.w * wv[j].w;
            a1 += p1.x * wv[j].x + p1.y * wv[j].y + p1.z * wv[j].z + p1.w * wv[j].w;
            a2 += p2.x * wv[j].x + p2.y * wv[j].y + p2.z * wv[j].z + p2.w * wv[j].w;
            a3 += p3.x * wv[j].x + p3.y * wv[j].y + p3.z * wv[j].z + p3.w * wv[j].w;
        }
        // 4 interleaved butterfly reductions (independent chains).
#pragma unroll
        for (int off = 16; off; off >>= 1) {
            a0 += __shfl_xor_sync(0xffffffffu, a0, off);
            a1 += __shfl_xor_sync(0xffffffffu, a1, off);
            a2 += __shfl_xor_sync(0xffffffffu, a2, off);
            a3 += __shfl_xor_sync(0xffffffffu, a3, off);
        }
        if (lane == 0) {
            float y0 = fmaxf(g * (a0 + bo - mn) * inv + bt, 0.0f);
            float y1 = fmaxf(g * (a1 + bo - mn) * inv + bt, 0.0f);
            float y2 = fmaxf(g * (a2 + bo - mn) * inv + bt, 0.0f);
            float y3 = fmaxf(g * (a3 + bo - mn) * inv + bt, 0.0f);
            out[(bb + 0) * CH + o] = y0;
            out[(bb + 1) * CH + o] = y1;
            out[(bb + 2) * CH + o] = y2;
            out[(bb + 3) * CH + o] = y3;
        }
    }
}

// ---------------------------------------------------------------------------
// Inputs (metadata order): x, pos_embed, conv_w, conv_b, bn_gamma, bn_beta,
// bn_mean, bn_var. Output: (32, 512, 1, 1) fp32.
// ---------------------------------------------------------------------------
extern "C" void kernel_launch(void* const* d_in, const int* in_sizes, int n_in,
                              void* d_out, int out_size) {
    const float* x     = (const float*)d_in[0];
    const float* pos   = (const float*)d_in[1];
    const float* w     = (const float*)d_in[2];
    const float* bias  = (const float*)d_in[3];
    const float* gamma = (const float*)d_in[4];
    const float* beta  = (const float*)d_in[5];
    const float* mean  = (const float*)d_in[6];
    const float* var   = (const float*)d_in[7];
    float* out = (float*)d_out;

    // Host-side: 1-D mean weights of the half-pixel bilinear 7->64 upsample
    // (jax triangle resize with edge renormalization == clamped lerp).
    A7 aw;
    {
        double acc[7] = {0, 0, 0, 0, 0, 0, 0};
        for (int i = 0; i < 64; ++i) {
            double s = (i + 0.5) * (7.0 / 64.0) - 0.5;
            s = s < 0.0 ? 0.0 : (s > 6.0 ? 6.0 : s);
            int i0 = (int)s;
            if (i0 > 5) i0 = 5;
            double f = s - (double)i0;
            acc[i0]     += 1.0 - f;
            acc[i0 + 1] += f;
        }
        for (int j = 0; j < 7; ++j) aw.a[j] = (float)(acc[j] / 64.0);
    }

    pool_kernel<<<BATCH * CH, 128>>>(x, pos, aw);

    // Secondary with programmatic (PDL) dependency on pool_kernel.
    cudaLaunchAttribute attr[1];
    attr[0].id = cudaLaunchAttributeProgrammaticStreamSerialization;
    attr[0].val.programmaticStreamSerializationAllowed = 1;
    cudaLaunchConfig_t cfg = {};
    cfg.gridDim  = dim3(64);
    cfg.blockDim = dim3(256);
    cfg.dynamicSmemBytes = 0;
    cfg.stream = 0;
    cfg.attrs = attr;
    cfg.numAttrs = 1;
    cudaError_t e = cudaLaunchKernelEx(&cfg, gemm_bn_kernel,
                                       w, bias, gamma, beta, mean, var, out);
    if (e != cudaSuccess) {
        // Fallback: plain stream-ordered launch (correct without PDL overlap).
        (void)cudaGetLastError();  // clear sticky error
        gemm_bn_kernel<<<64, 256>>>(w, bias, gamma, beta, mean, var, out);
    }
}